// round 13
// baseline (speedup 1.0000x reference)
#include <cuda_runtime.h>

// NavierStokesLossMAC: fused residual + masked MSE.
// Persistent CTAs (2/SM) walking contiguous y-strips (L1-carried vertical
// reuse, zero gpu-scope fences). NEW: x-halos come from warp shuffles of the
// already-loaded averaged quads; only lanes 0/31 touch memory (predicated,
// 2 wavefronts) -> ~27% fewer L1 wavefronts than per-thread scalar halos.
// Two launches: main + tiny finalize (fusion measured slower in R11/R12).

static constexpr int B = 8;
static constexpr int H = 1024;
static constexpr int W = 1024;
static constexpr float MU = 0.1f;
static constexpr float INV_DT = 0.25f;   // 1/DT, DT=4

static constexpr int RPB    = 2;                 // center rows per tile
static constexpr int TYB    = (H - 2) / RPB;     // 511 y-tiles per batch
static constexpr int NTILES = B * TYB;           // 4088 tiles total

__device__ double g_accum[B] = {0.0};            // fin kernel re-zeros

__device__ __forceinline__ void block_flush(float& local, int batch,
                                            float* s_part, int tid)
{
    #pragma unroll
    for (int o = 16; o > 0; o >>= 1)
        local += __shfl_xor_sync(0xffffffffu, local, o);
    const int lane = tid & 31, wid = tid >> 5;
    __syncthreads();                      // protect s_part reuse across flushes
    if (lane == 0) s_part[wid] = local;
    __syncthreads();
    if (tid < 32) {
        float v = (tid < 16) ? s_part[tid] : 0.0f;
        #pragma unroll
        for (int o = 8; o > 0; o >>= 1)
            v += __shfl_xor_sync(0xffffffffu, v, o);
        if (tid == 0)
            atomicAdd(&g_accum[batch], (double)v);    // RED to L2; no fence
    }
    local = 0.0f;
}

__global__ __launch_bounds__(512, 2) void ns_loss_kernel(
    const float* __restrict__ v_old,
    const float* __restrict__ v_new,
    const float* __restrict__ p_new,
    const int*   __restrict__ mask,
    int nb)
{
    __shared__ float s_part[16];
    const int tid  = threadIdx.x;
    const int lane = tid & 31;
    const bool is_l = (lane == 0), is_r = (lane == 31);
    const int p    = blockIdx.x;

    const int ts = (int)(((long long)p * NTILES) / nb);        // strip start
    const int te = (int)(((long long)(p + 1) * NTILES) / nb);  // strip end

    const size_t plane = (size_t)H * W;

    float local = 0.0f;
    int curB = ts / TYB;

    for (int t = ts; t < te; ++t) {
        const int batch = t / TYB;
        const int ytile = t - batch * TYB;
        if (batch != curB) {                 // uniform across block
            block_flush(local, curB, s_part, tid);
            curB = batch;
        }

        const int y  = 1 + ytile * RPB + (tid >> 8);   // center row, 1..1022
        const int x0 = (tid & 255) * 4;

        const float* uo = v_old + (size_t)batch * 2 * plane;   // ch 0 = u
        const float* wo = uo + plane;                           // ch 1 = w
        const float* un = v_new + (size_t)batch * 2 * plane;
        const float* wn = un + plane;
        const float* pp = p_new + (size_t)batch * plane;
        const int*   mm = mask  + (size_t)batch * plane;

        const int row = y * W + x0;
        const int rym = row - W;
        const int ryp = row + W;

        // ---- vectorized loads (all independent) ----
        float4 uo_c = *(const float4*)(uo + row);
        float4 un_c = *(const float4*)(un + row);
        float4 wo_c = *(const float4*)(wo + row);
        float4 wn_c = *(const float4*)(wn + row);

        float4 uo_m = *(const float4*)(uo + rym);
        float4 un_m = *(const float4*)(un + rym);
        float4 uo_p = *(const float4*)(uo + ryp);
        float4 un_p = *(const float4*)(un + ryp);
        float4 wo_m = *(const float4*)(wo + rym);
        float4 wn_m = *(const float4*)(wn + rym);
        float4 wo_p = *(const float4*)(wo + ryp);
        float4 wn_p = *(const float4*)(wn + ryp);

        float4 p_c4 = *(const float4*)(pp + row);
        float4 p_m4 = *(const float4*)(pp + rym);
        int4   mk   = *(const int4*)(mm + row);

        // ---- warp-edge halos: only lanes 0/31 load (2 wavefronts each) ----
        float uE = 0.0f, wE = 0.0f, pE = 0.0f;
        if (is_l | is_r) {
            const int eo = is_l ? (row - 1) : (row + 4);  // in-plane for y>=1
            uE = 0.5f * (uo[eo] + un[eo]);
            wE = 0.5f * (wo[eo] + wn[eo]);
            if (is_l) pE = pp[row - 1];
        }

        // ---- time-averaged center quads ----
        const float ucx = 0.5f*(uo_c.x+un_c.x), ucy = 0.5f*(uo_c.y+un_c.y);
        const float ucz = 0.5f*(uo_c.z+un_c.z), ucw = 0.5f*(uo_c.w+un_c.w);
        const float wcx = 0.5f*(wo_c.x+wn_c.x), wcy = 0.5f*(wo_c.y+wn_c.y);
        const float wcz = 0.5f*(wo_c.z+wn_c.z), wcw = 0.5f*(wo_c.w+wn_c.w);

        // ---- halos via shuffle (neighbor lane's .w / .x), edges patched ----
        float u_l = __shfl_up_sync(0xffffffffu, ucw, 1);  if (is_l) u_l = uE;
        float u_r = __shfl_down_sync(0xffffffffu, ucx, 1); if (is_r) u_r = uE;
        float w_lh = __shfl_up_sync(0xffffffffu, wcw, 1);  if (is_l) w_lh = wE;
        float w_rh = __shfl_down_sync(0xffffffffu, wcx, 1); if (is_r) w_rh = wE;
        float p_lh = __shfl_up_sync(0xffffffffu, p_c4.w, 1); if (is_l) p_lh = pE;

        const float uc6[6] = {u_l, ucx, ucy, ucz, ucw, u_r};
        const float wc6[6] = {w_lh, wcx, wcy, wcz, wcw, w_rh};
        const float pc5[5] = {p_lh, p_c4.x, p_c4.y, p_c4.z, p_c4.w};

        float uym[4] = {0.5f*(uo_m.x+un_m.x), 0.5f*(uo_m.y+un_m.y), 0.5f*(uo_m.z+un_m.z), 0.5f*(uo_m.w+un_m.w)};
        float uyp[4] = {0.5f*(uo_p.x+un_p.x), 0.5f*(uo_p.y+un_p.y), 0.5f*(uo_p.z+un_p.z), 0.5f*(uo_p.w+un_p.w)};
        float wym[4] = {0.5f*(wo_m.x+wn_m.x), 0.5f*(wo_m.y+wn_m.y), 0.5f*(wo_m.z+wn_m.z), 0.5f*(wo_m.w+wn_m.w)};
        float wyp[4] = {0.5f*(wo_p.x+wn_p.x), 0.5f*(wo_p.y+wn_p.y), 0.5f*(wo_p.z+wn_p.z), 0.5f*(wo_p.w+wn_p.w)};

        float du4[4] = {(un_c.x-uo_c.x)*INV_DT, (un_c.y-uo_c.y)*INV_DT, (un_c.z-uo_c.z)*INV_DT, (un_c.w-uo_c.w)*INV_DT};
        float dw4[4] = {(wn_c.x-wo_c.x)*INV_DT, (wn_c.y-wo_c.y)*INV_DT, (wn_c.z-wo_c.z)*INV_DT, (wn_c.w-wo_c.w)*INV_DT};

        float pym[4] = {p_m4.x, p_m4.y, p_m4.z, p_m4.w};
        int   mk4[4] = {mk.x, mk.y, mk.z, mk.w};

        #pragma unroll
        for (int j = 0; j < 4; ++j) {
            const float u_c  = uc6[j+1], u_xm = uc6[j], u_xp = uc6[j+2];
            const float w_c  = wc6[j+1], w_xm = wc6[j], w_xp = wc6[j+2];
            const float u_ym = uym[j],  u_yp = uyp[j];
            const float w_ym = wym[j],  w_yp = wyp[j];

            // res_x (RHO = 1)
            float rx = dw4[j]
                     + w_c * 0.5f * (w_xp - w_xm)
                     + 0.5f * ( 0.5f*(u_c + u_xm) * (w_c - w_ym)
                              + 0.5f*(u_c + u_xp) * (w_yp - w_c) )
                     + (pc5[j+1] - pc5[j])
                     - MU * (w_xm + w_xp + w_ym + w_yp - 4.0f * w_c);

            // res_y
            float ry = du4[j]
                     + u_c * 0.5f * (u_yp - u_ym)
                     + 0.5f * ( 0.5f*(w_c + w_ym) * (u_c - u_xm)
                              + 0.5f*(w_c + w_yp) * (u_xp - u_c) )
                     + (pc5[j+1] - pym[j])
                     - MU * (u_xm + u_xp + u_ym + u_yp - 4.0f * u_c);

            const float mf = (float)mk4[j];
            rx *= mf;
            ry *= mf;

            const int x = x0 + j;
            if (x >= 1 && x <= W - 2)
                local += rx * rx + ry * ry;
        }
    }

    block_flush(local, curB, s_part, tid);
}

__global__ void ns_fin_kernel(float* __restrict__ out) {
    const int i = threadIdx.x;
    if (i < B) {
        const double inv_cnt = 1.0 / ((double)(H - 2) * (double)(W - 2));
        out[i] = (float)(g_accum[i] * inv_cnt);
        g_accum[i] = 0.0;                        // reset for next graph replay
    }
}

extern "C" void kernel_launch(void* const* d_in, const int* in_sizes, int n_in,
                              void* d_out, int out_size) {
    const float* v_old = (const float*)d_in[0];
    const float* v_new = (const float*)d_in[1];
    const float* p_new = (const float*)d_in[2];
    const int*   mask  = (const int*)d_in[3];
    float* out = (float*)d_out;

    int dev = 0, sms = 148;
    cudaGetDevice(&dev);
    cudaDeviceGetAttribute(&sms, cudaDevAttrMultiProcessorCount, dev);
    const int nb = 2 * sms;                      // one wave, 2 blocks/SM

    ns_loss_kernel<<<nb, 512>>>(v_old, v_new, p_new, mask, nb);
    ns_fin_kernel<<<1, 32>>>(out);
}

// round 16
// speedup vs baseline: 2.2209x; 2.2209x over previous
#include <cuda_runtime.h>

// NavierStokesLossMAC: fused residual + masked MSE.
// R10 winner body: persistent CTAs (2/SM) walking contiguous y-strips so
// inter-tile row overlap is re-served from this SM's L1 (L1D persists within
// a launch; zero gpu-scope fences = zero CCTL.IVALL). Per-tile: 512 threads,
// 2 center rows, direct float4 loads + scalar halos, all independent (max
// MLP). NEW vs R10: finalize kernel launched with PDL so its launch latency
// overlaps the main kernel instead of serializing after it.

static constexpr int B = 8;
static constexpr int H = 1024;
static constexpr int W = 1024;
static constexpr float MU = 0.1f;
static constexpr float INV_DT = 0.25f;   // 1/DT, DT=4

static constexpr int RPB    = 2;                 // center rows per tile
static constexpr int TYB    = (H - 2) / RPB;     // 511 y-tiles per batch
static constexpr int NTILES = B * TYB;           // 4088 tiles total

__device__ double g_accum[B] = {0.0};            // fin kernel re-zeros

__device__ __forceinline__ void block_flush(float& local, int batch,
                                            float* s_part, int tid)
{
    #pragma unroll
    for (int o = 16; o > 0; o >>= 1)
        local += __shfl_xor_sync(0xffffffffu, local, o);
    const int lane = tid & 31, wid = tid >> 5;
    __syncthreads();                      // protect s_part reuse across flushes
    if (lane == 0) s_part[wid] = local;
    __syncthreads();
    if (tid < 32) {
        float v = (tid < 16) ? s_part[tid] : 0.0f;
        #pragma unroll
        for (int o = 8; o > 0; o >>= 1)
            v += __shfl_xor_sync(0xffffffffu, v, o);
        if (tid == 0)
            atomicAdd(&g_accum[batch], (double)v);    // RED to L2; no fence
    }
    local = 0.0f;
}

__global__ __launch_bounds__(512, 2) void ns_loss_kernel(
    const float* __restrict__ v_old,
    const float* __restrict__ v_new,
    const float* __restrict__ p_new,
    const int*   __restrict__ mask,
    int nb)
{
    __shared__ float s_part[16];
    const int tid = threadIdx.x;
    const int p   = blockIdx.x;

    const int ts = (int)(((long long)p * NTILES) / nb);        // strip start
    const int te = (int)(((long long)(p + 1) * NTILES) / nb);  // strip end

    const size_t plane = (size_t)H * W;

    float local = 0.0f;
    int curB = ts / TYB;

    for (int t = ts; t < te; ++t) {
        const int batch = t / TYB;
        const int ytile = t - batch * TYB;
        if (batch != curB) {                 // uniform across block
            block_flush(local, curB, s_part, tid);
            curB = batch;
        }

        const int y  = 1 + ytile * RPB + (tid >> 8);   // center row, 1..1022
        const int x0 = (tid & 255) * 4;

        const float* uo = v_old + (size_t)batch * 2 * plane;   // ch 0 = u
        const float* wo = uo + plane;                           // ch 1 = w
        const float* un = v_new + (size_t)batch * 2 * plane;
        const float* wn = un + plane;
        const float* pp = p_new + (size_t)batch * plane;
        const int*   mm = mask  + (size_t)batch * plane;

        const int row = y * W + x0;
        const int rym = row - W;
        const int ryp = row + W;

        // ---- all loads issued up front, fully independent ----
        float4 uo_c = *(const float4*)(uo + row);
        float4 un_c = *(const float4*)(un + row);
        float4 wo_c = *(const float4*)(wo + row);
        float4 wn_c = *(const float4*)(wn + row);
        float uo_l = uo[row - 1], un_l = un[row - 1];
        float uo_r = uo[row + 4], un_r = un[row + 4];
        float wo_l = wo[row - 1], wn_l = wn[row - 1];
        float wo_r = wo[row + 4], wn_r = wn[row + 4];

        float4 uo_m = *(const float4*)(uo + rym);
        float4 un_m = *(const float4*)(un + rym);
        float4 uo_p = *(const float4*)(uo + ryp);
        float4 un_p = *(const float4*)(un + ryp);
        float4 wo_m = *(const float4*)(wo + rym);
        float4 wn_m = *(const float4*)(wn + rym);
        float4 wo_p = *(const float4*)(wo + ryp);
        float4 wn_p = *(const float4*)(wn + ryp);

        float4 p_c4 = *(const float4*)(pp + row);
        float  p_l  = pp[row - 1];
        float4 p_m4 = *(const float4*)(pp + rym);
        int4   mk   = *(const int4*)(mm + row);

        // ---- time-averaged velocities & dt terms ----
        float uc6[6], wc6[6];
        uc6[0] = 0.5f * (uo_l + un_l);
        uc6[1] = 0.5f * (uo_c.x + un_c.x); uc6[2] = 0.5f * (uo_c.y + un_c.y);
        uc6[3] = 0.5f * (uo_c.z + un_c.z); uc6[4] = 0.5f * (uo_c.w + un_c.w);
        uc6[5] = 0.5f * (uo_r + un_r);
        wc6[0] = 0.5f * (wo_l + wn_l);
        wc6[1] = 0.5f * (wo_c.x + wn_c.x); wc6[2] = 0.5f * (wo_c.y + wn_c.y);
        wc6[3] = 0.5f * (wo_c.z + wn_c.z); wc6[4] = 0.5f * (wo_c.w + wn_c.w);
        wc6[5] = 0.5f * (wo_r + wn_r);

        float uym[4] = {0.5f*(uo_m.x+un_m.x), 0.5f*(uo_m.y+un_m.y), 0.5f*(uo_m.z+un_m.z), 0.5f*(uo_m.w+un_m.w)};
        float uyp[4] = {0.5f*(uo_p.x+un_p.x), 0.5f*(uo_p.y+un_p.y), 0.5f*(uo_p.z+un_p.z), 0.5f*(uo_p.w+un_p.w)};
        float wym[4] = {0.5f*(wo_m.x+wn_m.x), 0.5f*(wo_m.y+wn_m.y), 0.5f*(wo_m.z+wn_m.z), 0.5f*(wo_m.w+wn_m.w)};
        float wyp[4] = {0.5f*(wo_p.x+wn_p.x), 0.5f*(wo_p.y+wn_p.y), 0.5f*(wo_p.z+wn_p.z), 0.5f*(wo_p.w+wn_p.w)};

        float du4[4] = {(un_c.x-uo_c.x)*INV_DT, (un_c.y-uo_c.y)*INV_DT, (un_c.z-uo_c.z)*INV_DT, (un_c.w-uo_c.w)*INV_DT};
        float dw4[4] = {(wn_c.x-wo_c.x)*INV_DT, (wn_c.y-wo_c.y)*INV_DT, (wn_c.z-wo_c.z)*INV_DT, (wn_c.w-wo_c.w)*INV_DT};

        float pc5[5] = {p_l, p_c4.x, p_c4.y, p_c4.z, p_c4.w};
        float pym[4] = {p_m4.x, p_m4.y, p_m4.z, p_m4.w};
        int   mk4[4] = {mk.x, mk.y, mk.z, mk.w};

        #pragma unroll
        for (int j = 0; j < 4; ++j) {
            const float u_c  = uc6[j+1], u_xm = uc6[j], u_xp = uc6[j+2];
            const float w_c  = wc6[j+1], w_xm = wc6[j], w_xp = wc6[j+2];
            const float u_ym = uym[j],  u_yp = uyp[j];
            const float w_ym = wym[j],  w_yp = wyp[j];

            // res_x (RHO = 1)
            float rx = dw4[j]
                     + w_c * 0.5f * (w_xp - w_xm)
                     + 0.5f * ( 0.5f*(u_c + u_xm) * (w_c - w_ym)
                              + 0.5f*(u_c + u_xp) * (w_yp - w_c) )
                     + (pc5[j+1] - pc5[j])
                     - MU * (w_xm + w_xp + w_ym + w_yp - 4.0f * w_c);

            // res_y
            float ry = du4[j]
                     + u_c * 0.5f * (u_yp - u_ym)
                     + 0.5f * ( 0.5f*(w_c + w_ym) * (u_c - u_xm)
                              + 0.5f*(w_c + w_yp) * (u_xp - u_c) )
                     + (pc5[j+1] - pym[j])
                     - MU * (u_xm + u_xp + u_ym + u_yp - 4.0f * u_c);

            const float mf = (float)mk4[j];
            rx *= mf;
            ry *= mf;

            const int x = x0 + j;
            if (x >= 1 && x <= W - 2)
                local += rx * rx + ry * ry;
        }
    }

    block_flush(local, curB, s_part, tid);
}

__global__ void ns_fin_kernel(float* __restrict__ out) {
    // PDL: wait for the primary grid (ns_loss_kernel) to fully complete.
    cudaGridDependencySynchronize();
    const int i = threadIdx.x;
    if (i < B) {
        const double inv_cnt = 1.0 / ((double)(H - 2) * (double)(W - 2));
        out[i] = (float)(g_accum[i] * inv_cnt);
        g_accum[i] = 0.0;                        // reset for next graph replay
    }
}

extern "C" void kernel_launch(void* const* d_in, const int* in_sizes, int n_in,
                              void* d_out, int out_size) {
    const float* v_old = (const float*)d_in[0];
    const float* v_new = (const float*)d_in[1];
    const float* p_new = (const float*)d_in[2];
    const int*   mask  = (const int*)d_in[3];
    float* out = (float*)d_out;

    int dev = 0, sms = 148;
    cudaGetDevice(&dev);
    cudaDeviceGetAttribute(&sms, cudaDevAttrMultiProcessorCount, dev);
    const int nb = 2 * sms;                      // one wave, 2 blocks/SM

    ns_loss_kernel<<<nb, 512>>>(v_old, v_new, p_new, mask, nb);

    // Finalize with programmatic dependent launch: launch overhead overlaps
    // the primary kernel; cudaGridDependencySynchronize() inside provides the
    // completion ordering.
    cudaLaunchConfig_t cfg = {};
    cfg.gridDim  = dim3(1, 1, 1);
    cfg.blockDim = dim3(32, 1, 1);
    cudaLaunchAttribute attr[1];
    attr[0].id = cudaLaunchAttributeProgrammaticStreamSerialization;
    attr[0].val.programmaticStreamSerializationAllowed = 1;
    cfg.attrs = attr;
    cfg.numAttrs = 1;
    cudaLaunchKernelEx(&cfg, ns_fin_kernel, out);
}